// round 1
// baseline (speedup 1.0000x reference)
#include <cuda_runtime.h>

#define NN     8
#define CC     21
#define HWP    262144      // 512*512
#define OLDCL  16
#define IGN    255
#define NCLS   6           // classes that can appear as labels: 0, 16..20

// scratch: per-sample [T[0..5], H[0..5], vcount, pad...] -> 16 floats per sample
__device__ float g_part[NN * 16];

__global__ void zero_k() {
    int i = threadIdx.x;
    if (i < NN * 16) g_part[i] = 0.0f;
}

__device__ __forceinline__ void pixel_acc(int tj, float s, float s16, float sel,
                                          float* accT, float* accH, float& vc) {
    int l = (tj < OLDCL) ? 0 : tj;
    float L21 = __logf(s);
    float lp  = (l == 0) ? (__logf(s16) - L21) : (sel - L21);
    bool valid = (tj != IGN);
    int idx = (l == 0) ? 0 : (l - (OLDCL - 1));   // 0, or 1..5 for classes 16..20
#pragma unroll
    for (int k = 0; k < NCLS; k++) {
        bool m = valid && (idx == k);
        if (m) { accT[k] += lp; accH[k] += 1.0f; }
    }
    vc += valid ? 1.0f : 0.0f;
}

__global__ __launch_bounds__(256) void main_k(const float* __restrict__ in,
                                              const int* __restrict__ tg) {
    int n = blockIdx.y;
    const float* base = in + (size_t)n * CC * HWP;
    const int*   t    = tg + (size_t)n * HWP;

    float accT[NCLS] = {0, 0, 0, 0, 0, 0};
    float accH[NCLS] = {0, 0, 0, 0, 0, 0};
    float vc = 0.0f;

    int stride = gridDim.x * blockDim.x;
    for (int g = blockIdx.x * blockDim.x + threadIdx.x; g < HWP / 4; g += stride) {
        int p = g * 4;
        int4 tv = *reinterpret_cast<const int4*>(t + p);
        int l0 = (tv.x < OLDCL) ? 0 : tv.x;
        int l1 = (tv.y < OLDCL) ? 0 : tv.y;
        int l2 = (tv.z < OLDCL) ? 0 : tv.z;
        int l3 = (tv.w < OLDCL) ? 0 : tv.w;

        float4 s   = make_float4(0.f, 0.f, 0.f, 0.f);
        float4 s16 = make_float4(0.f, 0.f, 0.f, 0.f);
        float4 sel = make_float4(0.f, 0.f, 0.f, 0.f);
#pragma unroll
        for (int c = 0; c < CC; c++) {
            float4 xv = *reinterpret_cast<const float4*>(base + (size_t)c * HWP + p);
            s.x += __expf(xv.x);
            s.y += __expf(xv.y);
            s.z += __expf(xv.z);
            s.w += __expf(xv.w);
            if (c == OLDCL - 1) s16 = s;          // sum over channels 0..15
            sel.x = (c == l0) ? xv.x : sel.x;
            sel.y = (c == l1) ? xv.y : sel.y;
            sel.z = (c == l2) ? xv.z : sel.z;
            sel.w = (c == l3) ? xv.w : sel.w;
        }
        pixel_acc(tv.x, s.x, s16.x, sel.x, accT, accH, vc);
        pixel_acc(tv.y, s.y, s16.y, sel.y, accT, accH, vc);
        pixel_acc(tv.z, s.z, s16.z, sel.z, accT, accH, vc);
        pixel_acc(tv.w, s.w, s16.w, sel.w, accT, accH, vc);
    }

    // block reduction of 13 values (6 T + 6 H + vcount)
    float vals[13];
#pragma unroll
    for (int k = 0; k < NCLS; k++) { vals[k] = accT[k]; vals[k + NCLS] = accH[k]; }
    vals[12] = vc;

    __shared__ float sh[8][13];
    int lane = threadIdx.x & 31;
    int wid  = threadIdx.x >> 5;
#pragma unroll
    for (int k = 0; k < 13; k++) {
        float v = vals[k];
        v += __shfl_down_sync(0xffffffffu, v, 16);
        v += __shfl_down_sync(0xffffffffu, v, 8);
        v += __shfl_down_sync(0xffffffffu, v, 4);
        v += __shfl_down_sync(0xffffffffu, v, 2);
        v += __shfl_down_sync(0xffffffffu, v, 1);
        if (lane == 0) sh[wid][k] = v;
    }
    __syncthreads();
    if (wid == 0) {
#pragma unroll
        for (int k = 0; k < 13; k++) {
            float v = (lane < 8) ? sh[lane][k] : 0.0f;
            v += __shfl_down_sync(0xffffffffu, v, 4);
            v += __shfl_down_sync(0xffffffffu, v, 2);
            v += __shfl_down_sync(0xffffffffu, v, 1);
            if (lane == 0) atomicAdd(&g_part[n * 16 + k], v);
        }
    }
}

__global__ void fin_k(float* out) {
    int lane = threadIdx.x;
    float num = 0.0f, den = 0.0f;
    if (lane < NN) {
        float T[NCLS], H[NCLS];
#pragma unroll
        for (int k = 0; k < NCLS; k++) {
            T[k] = g_part[lane * 16 + k];
            H[k] = g_part[lane * 16 + NCLS + k];
        }
        float vcn = g_part[lane * 16 + 12];
        float hs[NCLS], S = 0.0f;
#pragma unroll
        for (int k = 0; k < NCLS; k++) {
            hs[k] = (H[k] == 0.0f) ? 1.0f : H[k];   // empty classes -> 1 (RATIO=1)
            S += hs[k];
        }
        float c = 0.0f;
#pragma unroll
        for (int k = 0; k < NCLS; k++) c += (S / hs[k]) * T[k];   // weight = S/h
        num = c;
        den = vcn;
    }
    num += __shfl_down_sync(0xffffffffu, num, 4);
    den += __shfl_down_sync(0xffffffffu, den, 4);
    num += __shfl_down_sync(0xffffffffu, num, 2);
    den += __shfl_down_sync(0xffffffffu, den, 2);
    num += __shfl_down_sync(0xffffffffu, num, 1);
    den += __shfl_down_sync(0xffffffffu, den, 1);
    if (lane == 0) out[0] = -num / den;
}

extern "C" void kernel_launch(void* const* d_in, const int* in_sizes, int n_in,
                              void* d_out, int out_size) {
    const float* in;
    const int*   tg;
    // inputs tensor is the big one (N*C*H*W); targets is N*H*W
    if (in_sizes[0] > in_sizes[1]) {
        in = (const float*)d_in[0];
        tg = (const int*)d_in[1];
    } else {
        in = (const float*)d_in[1];
        tg = (const int*)d_in[0];
    }
    zero_k<<<1, 128>>>();
    dim3 grid(64, NN);
    main_k<<<grid, 256>>>(in, tg);
    fin_k<<<1, 32>>>((float*)d_out);
}